// round 10
// baseline (speedup 1.0000x reference)
#include <cuda_runtime.h>
#include <cuda_fp16.h>
#include <cstdint>

#define B_DIM   512
#define E_DIM   8
#define IN_DIM  1024
#define OUT_DIM 1024

#define MT 128
#define NT 128
#define KC 64                        // K chunk (fp16) = 128B row
#define ZSPLIT 8
#define NCHUNK (IN_DIM / KC)         // 16 (one expert per CTA)
#define THREADS 256
#define STAGES 3

#define TILE_BYTES (128 * 128)       // 16KB per operand tile
#define STAGE_BYTES (2 * TILE_BYTES) // A + B per stage (32KB)
#define SMEM_TOTAL (STAGES * STAGE_BYTES)   // 96KB

// scratch (no cudaMalloc allowed)
__device__ __half g_xs[E_DIM * B_DIM * IN_DIM];      // pre-blended A planes, 8MB
__device__ __half g_wh[E_DIM * OUT_DIM * IN_DIM];    // fp16 W, 16.8MB
__device__ float  g_partial[ZSPLIT * B_DIM * OUT_DIM];

// ---------- helpers ----------
__device__ __forceinline__ uint32_t smem_u32(const void* p) {
    uint32_t a;
    asm("{ .reg .u64 t; cvta.to.shared.u64 t, %1; cvt.u32.u64 %0, t; }" : "=r"(a) : "l"(p));
    return a;
}
__device__ __forceinline__ void cp16(uint32_t dst, const void* src) {
    asm volatile("cp.async.cg.shared.global [%0], [%1], 16;" :: "r"(dst), "l"(src));
}
__device__ __forceinline__ void ldsm_x4(uint32_t* r, uint32_t addr) {
    asm volatile("ldmatrix.sync.aligned.m8n8.x4.shared.b16 {%0,%1,%2,%3}, [%4];"
                 : "=r"(r[0]), "=r"(r[1]), "=r"(r[2]), "=r"(r[3]) : "r"(addr));
}
__device__ __forceinline__ void mma_fp16(float* c, const uint32_t* a,
                                         uint32_t b0, uint32_t b1) {
    asm volatile(
        "mma.sync.aligned.m16n8k16.row.col.f32.f16.f16.f32 "
        "{%0,%1,%2,%3}, {%4,%5,%6,%7}, {%8,%9}, {%0,%1,%2,%3};"
        : "+f"(c[0]), "+f"(c[1]), "+f"(c[2]), "+f"(c[3])
        : "r"(a[0]), "r"(a[1]), "r"(a[2]), "r"(a[3]), "r"(b0), "r"(b1));
}
__device__ __forceinline__ uint32_t sw_off(int r, int kb) {
    return (uint32_t)(r * 128 + ((kb ^ (r & 7)) << 4));
}

// ---------- prep: W->fp16 and x->pre-blended fp16 planes (16 elems/thread) ----------
#define W_BLOCKS (E_DIM * OUT_DIM * IN_DIM / 16 / 256)   // 2048
#define X_BLOCKS (B_DIM * IN_DIM / 16 / 256)             // 128
__global__ __launch_bounds__(256)
void prep_kernel(const float* __restrict__ x,
                 const float* __restrict__ ew,
                 const float* __restrict__ W)
{
    if (blockIdx.x < W_BLOCKS) {
        const size_t idx = ((size_t)blockIdx.x * 256 + threadIdx.x) * 16;
        float4 v[4];
        #pragma unroll
        for (int j = 0; j < 4; ++j) v[j] = __ldg((const float4*)(W + idx + 4 * j));
        uint4 o[2];
        #pragma unroll
        for (int j = 0; j < 2; ++j) {
            __half2 a = __floats2half2_rn(v[2*j].x,   v[2*j].y);
            __half2 b = __floats2half2_rn(v[2*j].z,   v[2*j].w);
            __half2 c = __floats2half2_rn(v[2*j+1].x, v[2*j+1].y);
            __half2 d = __floats2half2_rn(v[2*j+1].z, v[2*j+1].w);
            o[j] = make_uint4(*(uint32_t*)&a, *(uint32_t*)&b,
                              *(uint32_t*)&c, *(uint32_t*)&d);
        }
        *(uint4*)(g_wh + idx)     = o[0];
        *(uint4*)(g_wh + idx + 8) = o[1];
    } else {
        const int idx = ((blockIdx.x - W_BLOCKS) * 256 + threadIdx.x) * 16;
        const int b = idx >> 10;
        float4 v[4];
        #pragma unroll
        for (int j = 0; j < 4; ++j) v[j] = __ldg((const float4*)(x + idx + 4 * j));
        #pragma unroll
        for (int e = 0; e < E_DIM; ++e) {
            const float s = __ldg(&ew[b * E_DIM + e]);
            __half* dst = g_xs + (size_t)e * (B_DIM * IN_DIM) + idx;
            #pragma unroll
            for (int j = 0; j < 2; ++j) {
                __half2 a = __floats2half2_rn(v[2*j].x * s,   v[2*j].y * s);
                __half2 c = __floats2half2_rn(v[2*j].z * s,   v[2*j].w * s);
                __half2 d = __floats2half2_rn(v[2*j+1].x * s, v[2*j+1].y * s);
                __half2 f = __floats2half2_rn(v[2*j+1].z * s, v[2*j+1].w * s);
                *(uint4*)(dst + 8 * j) = make_uint4(*(uint32_t*)&a, *(uint32_t*)&c,
                                                    *(uint32_t*)&d, *(uint32_t*)&f);
            }
        }
    }
}

// ---------- GEMM: partial_e = (ew_e*x) @ W_e^T, 3-stage pipeline ----------
__global__ __launch_bounds__(THREADS, 2)
void moe_gemm_kernel()
{
    extern __shared__ __align__(16) uint8_t smem[];
    const uint32_t sbase = smem_u32(smem);

    const int tid  = threadIdx.x;
    const int lane = tid & 31;
    const int wid  = tid >> 5;
    const int bn = blockIdx.x * NT;
    const int bm = blockIdx.y * MT;
    const int e  = blockIdx.z;

    const int wm = wid >> 2;        // 0..1 -> 64 rows
    const int wn = wid & 3;         // 0..3 -> 32 cols

    const __half* ap = g_xs + (size_t)e * (B_DIM * IN_DIM);
    const __half* bp = g_wh + (size_t)e * (OUT_DIM * IN_DIM);

    float acc[16][4];
    #pragma unroll
    for (int i = 0; i < 16; ++i)
        #pragma unroll
        for (int j = 0; j < 4; ++j) acc[i][j] = 0.0f;

    auto issue = [&](int c, int stg) {
        const int k0 = c * KC;
        const uint32_t base = sbase + stg * STAGE_BYTES;
        #pragma unroll
        for (int j = 0; j < 4; ++j) {
            const int cid = tid + j * 256;     // 0..1023
            const int row = cid >> 3;
            const int kb  = cid & 7;
            const uint32_t d = sw_off(row, kb);
            const int goff = k0 + kb * 8;
            cp16(base + d,              ap + (size_t)(bm + row) * IN_DIM + goff);
            cp16(base + TILE_BYTES + d, bp + (size_t)(bn + row) * IN_DIM + goff);
        }
        asm volatile("cp.async.commit_group;" ::: "memory");
    };

    issue(0, 0);
    issue(1, 1);

    for (int c = 0; c < NCHUNK; ++c) {
        const int stg = c % STAGES;
        asm volatile("cp.async.wait_group 1;" ::: "memory");  // chunk c landed
        __syncthreads();  // publishes chunk c; retires readers of buf (c-1)%3

        if (c + 2 < NCHUNK) issue(c + 2, (c + 2) % STAGES);   // overwrites (c-1)%3: safe

        const uint32_t uA = sbase + stg * STAGE_BYTES;
        const uint32_t uB = uA + TILE_BYTES;

        #pragma unroll
        for (int ks = 0; ks < 4; ++ks) {
            uint32_t ah[4][4];
            const int ar  = lane & 15;
            const int akb = ks * 2 + (lane >> 4);
            #pragma unroll
            for (int mt = 0; mt < 4; ++mt) {
                const int r = wm * 64 + mt * 16 + ar;
                ldsm_x4(ah[mt], uA + sw_off(r, akb));
            }
            uint32_t bh[2][4];
            #pragma unroll
            for (int p = 0; p < 2; ++p) {
                const int r  = wn * 32 + p * 16 + (lane & 7) + ((lane >> 4) & 1) * 8;
                const int kb = ks * 2 + ((lane >> 3) & 1);
                ldsm_x4(bh[p], uB + sw_off(r, kb));
            }
            #pragma unroll
            for (int mt = 0; mt < 4; ++mt)
                #pragma unroll
                for (int p = 0; p < 2; ++p)
                    #pragma unroll
                    for (int sub = 0; sub < 2; ++sub)
                        mma_fp16(acc[mt * 4 + p * 2 + sub], ah[mt],
                                 bh[p][sub * 2], bh[p][sub * 2 + 1]);
        }
    }

    // epilogue -> partial plane e
    const int tr = lane >> 2;
    const int tc = (lane & 3) * 2;
    #pragma unroll
    for (int mt = 0; mt < 4; ++mt) {
        const int row = bm + wm * 64 + mt * 16 + tr;
        float* base = g_partial + ((size_t)e * B_DIM + row) * OUT_DIM + bn + wn * 32;
        #pragma unroll
        for (int nt = 0; nt < 4; ++nt) {
            const float* a4 = acc[mt * 4 + nt];
            *(float2*)(base + nt * 8 + tc)                       = make_float2(a4[0], a4[1]);
            *(float2*)(base + 8 * (size_t)OUT_DIM + nt * 8 + tc) = make_float2(a4[2], a4[3]);
        }
    }
}

// ---------- combine: sum 8 partial planes + blended bias (4 floats/thread) ----------
__global__ __launch_bounds__(256)
void combine_kernel(const float* __restrict__ ew,
                    const float* __restrict__ bias,
                    float* __restrict__ out)
{
    const int idx = (blockIdx.x * 256 + threadIdx.x) * 4;
    const int b   = idx >> 10;
    const int o   = idx & 1023;
    const size_t off = (size_t)b * OUT_DIM + o;
    const size_t plane = (size_t)B_DIM * OUT_DIM;

    float4 p[E_DIM];
    #pragma unroll
    for (int e = 0; e < E_DIM; ++e)
        p[e] = *(const float4*)&g_partial[e * plane + off];

    float w[E_DIM];
    #pragma unroll
    for (int e = 0; e < E_DIM; ++e) w[e] = __ldg(&ew[b * E_DIM + e]);

    float4 s = make_float4(0.f, 0.f, 0.f, 0.f);
    #pragma unroll
    for (int e = 0; e < E_DIM; ++e) {
        s.x += p[e].x; s.y += p[e].y; s.z += p[e].z; s.w += p[e].w;
    }
    #pragma unroll
    for (int e = 0; e < E_DIM; ++e) {
        const float4 bv = *(const float4*)&bias[e * OUT_DIM + o];
        s.x = fmaf(w[e], bv.x, s.x); s.y = fmaf(w[e], bv.y, s.y);
        s.z = fmaf(w[e], bv.z, s.z); s.w = fmaf(w[e], bv.w, s.w);
    }
    *(float4*)(out + off) = s;
}

extern "C" void kernel_launch(void* const* d_in, const int* in_sizes, int n_in,
                              void* d_out, int out_size)
{
    const float* x    = (const float*)d_in[0];   // [512, 1024]
    const float* ew   = (const float*)d_in[1];   // [512, 8]
    const float* W    = (const float*)d_in[2];   // [8, 1024, 1024]
    const float* bias = (const float*)d_in[3];   // [8, 1024]
    float* out = (float*)d_out;

    prep_kernel<<<W_BLOCKS + X_BLOCKS, 256>>>(x, ew, W);

    cudaFuncSetAttribute(moe_gemm_kernel,
                         cudaFuncAttributeMaxDynamicSharedMemorySize, SMEM_TOTAL);
    dim3 grid(OUT_DIM / NT, B_DIM / MT, ZSPLIT);   // (8, 4, 8) = 256 CTAs
    moe_gemm_kernel<<<grid, THREADS, SMEM_TOTAL>>>();

    combine_kernel<<<B_DIM * OUT_DIM / 4 / 256, 256>>>(ew, bias, out);
}

// round 11
// speedup vs baseline: 1.1266x; 1.1266x over previous
#include <cuda_runtime.h>
#include <cuda_fp16.h>
#include <cstdint>

#define B_DIM   512
#define E_DIM   8
#define IN_DIM  1024
#define OUT_DIM 1024

#define MT 128
#define NT 128
#define KC 64                        // K chunk (fp16) = 128B row
#define ZSPLIT 8
#define NCHUNK (IN_DIM / KC)         // 16 (one expert per CTA)
#define THREADS 256

#define TILE_BYTES (128 * 128)       // 16KB per operand tile
#define BUFSZ (2 * TILE_BYTES)       // A + B
#define SMEM_TOTAL (2 * BUFSZ)       // 64KB double-buffered

// scratch (no cudaMalloc allowed)
__device__ __half g_xs[E_DIM * B_DIM * IN_DIM];      // pre-blended A planes, 8MB
__device__ __half g_wh[E_DIM * OUT_DIM * IN_DIM];    // fp16 W, 16.8MB
__device__ float  g_partial[ZSPLIT * B_DIM * OUT_DIM];

// ---------- helpers ----------
__device__ __forceinline__ uint32_t smem_u32(const void* p) {
    uint32_t a;
    asm("{ .reg .u64 t; cvta.to.shared.u64 t, %1; cvt.u32.u64 %0, t; }" : "=r"(a) : "l"(p));
    return a;
}
__device__ __forceinline__ void cp16(uint32_t dst, const void* src) {
    asm volatile("cp.async.cg.shared.global [%0], [%1], 16;" :: "r"(dst), "l"(src));
}
__device__ __forceinline__ void ldsm_x4(uint32_t* r, uint32_t addr) {
    asm volatile("ldmatrix.sync.aligned.m8n8.x4.shared.b16 {%0,%1,%2,%3}, [%4];"
                 : "=r"(r[0]), "=r"(r[1]), "=r"(r[2]), "=r"(r[3]) : "r"(addr));
}
__device__ __forceinline__ void mma_fp16(float* c, const uint32_t* a,
                                         uint32_t b0, uint32_t b1) {
    asm volatile(
        "mma.sync.aligned.m16n8k16.row.col.f32.f16.f16.f32 "
        "{%0,%1,%2,%3}, {%4,%5,%6,%7}, {%8,%9}, {%0,%1,%2,%3};"
        : "+f"(c[0]), "+f"(c[1]), "+f"(c[2]), "+f"(c[3])
        : "r"(a[0]), "r"(a[1]), "r"(a[2]), "r"(a[3]), "r"(b0), "r"(b1));
}
__device__ __forceinline__ uint32_t sw_off(int r, int kb) {
    return (uint32_t)(r * 128 + ((kb ^ (r & 7)) << 4));
}

// ---------- prep: W->fp16 and x->pre-blended fp16 planes (8 elems/thread) ----------
#define W_BLOCKS (E_DIM * OUT_DIM * IN_DIM / 8 / 256)   // 4096
#define X_BLOCKS (B_DIM * IN_DIM / 8 / 256)             // 256
__global__ __launch_bounds__(256)
void prep_kernel(const float* __restrict__ x,
                 const float* __restrict__ ew,
                 const float* __restrict__ W)
{
    if (blockIdx.x < W_BLOCKS) {
        const size_t idx = ((size_t)blockIdx.x * 256 + threadIdx.x) * 8;
        const float4 v0 = __ldg((const float4*)(W + idx));
        const float4 v1 = __ldg((const float4*)(W + idx + 4));
        __half2 a = __floats2half2_rn(v0.x, v0.y);
        __half2 b = __floats2half2_rn(v0.z, v0.w);
        __half2 c = __floats2half2_rn(v1.x, v1.y);
        __half2 d = __floats2half2_rn(v1.z, v1.w);
        *(uint4*)(g_wh + idx) = make_uint4(*(uint32_t*)&a, *(uint32_t*)&b,
                                           *(uint32_t*)&c, *(uint32_t*)&d);
    } else {
        const int idx = ((blockIdx.x - W_BLOCKS) * 256 + threadIdx.x) * 8;
        const int b = idx >> 10;
        const float4 v0 = __ldg((const float4*)(x + idx));
        const float4 v1 = __ldg((const float4*)(x + idx + 4));
        #pragma unroll
        for (int e = 0; e < E_DIM; ++e) {
            const float s = __ldg(&ew[b * E_DIM + e]);
            __half2 a = __floats2half2_rn(v0.x * s, v0.y * s);
            __half2 c = __floats2half2_rn(v0.z * s, v0.w * s);
            __half2 d = __floats2half2_rn(v1.x * s, v1.y * s);
            __half2 f = __floats2half2_rn(v1.z * s, v1.w * s);
            *(uint4*)(g_xs + (size_t)e * (B_DIM * IN_DIM) + idx) =
                make_uint4(*(uint32_t*)&a, *(uint32_t*)&c,
                           *(uint32_t*)&d, *(uint32_t*)&f);
        }
    }
}

// ---------- GEMM: partial_e = (ew_e*x) @ W_e^T ----------
__global__ __launch_bounds__(THREADS, 2)
void moe_gemm_kernel()
{
    extern __shared__ __align__(16) uint8_t smem[];
    const uint32_t sbase = smem_u32(smem);

    const int tid  = threadIdx.x;
    const int lane = tid & 31;
    const int wid  = tid >> 5;
    const int bn = blockIdx.x * NT;
    const int bm = blockIdx.y * MT;
    const int e  = blockIdx.z;

    const int wm = wid >> 2;        // 0..1 -> 64 rows
    const int wn = wid & 3;         // 0..3 -> 32 cols

    const __half* ap = g_xs + (size_t)e * (B_DIM * IN_DIM);
    const __half* bp = g_wh + (size_t)e * (OUT_DIM * IN_DIM);

    float acc[16][4];
    #pragma unroll
    for (int i = 0; i < 16; ++i)
        #pragma unroll
        for (int j = 0; j < 4; ++j) acc[i][j] = 0.0f;

    auto issue = [&](int c, int buf) {
        const int k0 = c * KC;
        const uint32_t base = sbase + buf * BUFSZ;
        #pragma unroll
        for (int j = 0; j < 4; ++j) {
            const int cid = tid + j * 256;     // 0..1023
            const int row = cid >> 3;
            const int kb  = cid & 7;
            const uint32_t d = sw_off(row, kb);
            const int goff = k0 + kb * 8;
            cp16(base + d,              ap + (size_t)(bm + row) * IN_DIM + goff);
            cp16(base + TILE_BYTES + d, bp + (size_t)(bn + row) * IN_DIM + goff);
        }
        asm volatile("cp.async.commit_group;" ::: "memory");
    };

    issue(0, 0);

    for (int c = 0; c < NCHUNK; ++c) {
        const int buf = c & 1;
        if (c + 1 < NCHUNK) {
            issue(c + 1, buf ^ 1);
            asm volatile("cp.async.wait_group 1;" ::: "memory");
        } else {
            asm volatile("cp.async.wait_group 0;" ::: "memory");
        }
        __syncthreads();

        const uint32_t uA = sbase + buf * BUFSZ;
        const uint32_t uB = uA + TILE_BYTES;

        #pragma unroll
        for (int ks = 0; ks < 4; ++ks) {
            uint32_t ah[4][4];
            const int ar  = lane & 15;
            const int akb = ks * 2 + (lane >> 4);
            #pragma unroll
            for (int mt = 0; mt < 4; ++mt) {
                const int r = wm * 64 + mt * 16 + ar;
                ldsm_x4(ah[mt], uA + sw_off(r, akb));
            }
            uint32_t bh[2][4];
            #pragma unroll
            for (int p = 0; p < 2; ++p) {
                const int r  = wn * 32 + p * 16 + (lane & 7) + ((lane >> 4) & 1) * 8;
                const int kb = ks * 2 + ((lane >> 3) & 1);
                ldsm_x4(bh[p], uB + sw_off(r, kb));
            }
            #pragma unroll
            for (int mt = 0; mt < 4; ++mt)
                #pragma unroll
                for (int p = 0; p < 2; ++p)
                    #pragma unroll
                    for (int sub = 0; sub < 2; ++sub)
                        mma_fp16(acc[mt * 4 + p * 2 + sub], ah[mt],
                                 bh[p][sub * 2], bh[p][sub * 2 + 1]);
        }
        __syncthreads();
    }

    // epilogue -> partial plane e
    const int tr = lane >> 2;
    const int tc = (lane & 3) * 2;
    #pragma unroll
    for (int mt = 0; mt < 4; ++mt) {
        const int row = bm + wm * 64 + mt * 16 + tr;
        float* base = g_partial + ((size_t)e * B_DIM + row) * OUT_DIM + bn + wn * 32;
        #pragma unroll
        for (int nt = 0; nt < 4; ++nt) {
            const float* a4 = acc[mt * 4 + nt];
            *(float2*)(base + nt * 8 + tc)                       = make_float2(a4[0], a4[1]);
            *(float2*)(base + 8 * (size_t)OUT_DIM + nt * 8 + tc) = make_float2(a4[2], a4[3]);
        }
    }
}

// ---------- combine: sum 8 partial planes + blended bias (2 floats/thread) ----------
__global__ __launch_bounds__(256)
void combine_kernel(const float* __restrict__ ew,
                    const float* __restrict__ bias,
                    float* __restrict__ out)
{
    const int idx = (blockIdx.x * 256 + threadIdx.x) * 2;   // 2 floats/thread
    const int b   = idx >> 10;
    const int o   = idx & 1023;
    const size_t off = (size_t)b * OUT_DIM + o;
    const size_t plane = (size_t)B_DIM * OUT_DIM;

    // 8 independent plane loads (MLP 8, L2-resident)
    float2 p[E_DIM];
    #pragma unroll
    for (int e = 0; e < E_DIM; ++e)
        p[e] = *(const float2*)&g_partial[e * plane + off];

    float2 bv[E_DIM];
    #pragma unroll
    for (int e = 0; e < E_DIM; ++e)
        bv[e] = *(const float2*)&bias[e * OUT_DIM + o];

    float w[E_DIM];
    #pragma unroll
    for (int e = 0; e < E_DIM; ++e) w[e] = __ldg(&ew[b * E_DIM + e]);

    float sx = 0.f, sy = 0.f;
    #pragma unroll
    for (int e = 0; e < E_DIM; ++e) { sx += p[e].x; sy += p[e].y; }
    #pragma unroll
    for (int e = 0; e < E_DIM; ++e) {
        sx = fmaf(w[e], bv[e].x, sx);
        sy = fmaf(w[e], bv[e].y, sy);
    }
    *(float2*)(out + off) = make_float2(sx, sy);
}

extern "C" void kernel_launch(void* const* d_in, const int* in_sizes, int n_in,
                              void* d_out, int out_size)
{
    const float* x    = (const float*)d_in[0];   // [512, 1024]
    const float* ew   = (const float*)d_in[1];   // [512, 8]
    const float* W    = (const float*)d_in[2];   // [8, 1024, 1024]
    const float* bias = (const float*)d_in[3];   // [8, 1024]
    float* out = (float*)d_out;

    prep_kernel<<<W_BLOCKS + X_BLOCKS, 256>>>(x, ew, W);

    cudaFuncSetAttribute(moe_gemm_kernel,
                         cudaFuncAttributeMaxDynamicSharedMemorySize, SMEM_TOTAL);
    dim3 grid(OUT_DIM / NT, B_DIM / MT, ZSPLIT);   // (8, 4, 8) = 256 CTAs
    moe_gemm_kernel<<<grid, THREADS, SMEM_TOTAL>>>();

    combine_kernel<<<B_DIM * OUT_DIM / 2 / 256, 256>>>(ew, bias, out);
}